// round 9
// baseline (speedup 1.0000x reference)
#include <cuda_runtime.h>
#include <cuda_fp16.h>

// BlurNet: fake_B = w * mean_k bilinear(fake_S, pix + t_k*20*blurmap) + bias
//          offsets_flat[b, 2k+c] = t_k * 20 * blurmap[b, c],  t_k = (7-k)/7
// B=8, C=3, H=W=256. Output: fake_B (B*3*H*W) then offsets (B*30*H*W), f32.
//
// R9 = R3 verbatim (proven best: interleaved offset stores ride the LDS-stall
// shadow; phase-separating them measured +1..2us in R4/R7/R8) with ONE change:
// vectorized halo fill (float4 LDG + STS.128, named scalars only — R5's
// register-array spill bug avoided).
// Gather layout: Ap[i]=(c0,c1)@x0,x1 8B LDS.64; Cp[i]=(c2)@x0,x1 4B LDS.32.

#define H 256
#define W 256
#define HW (H * W)
#define BATCH 8
#define TILE 32
#define HALO 20
#define TDIM (TILE + 2 * HALO)   // 72
#define NTHREADS 256

__global__ __launch_bounds__(NTHREADS, 3)
void blurnet_kernel(const float* __restrict__ fake_S,
                    const float* __restrict__ blurmap,
                    const float* __restrict__ weight,
                    const float* __restrict__ bias,
                    float* __restrict__ out_fb,
                    float* __restrict__ out_off)
{
    extern __shared__ __align__(16) unsigned char smem_raw[];
    uint2*   Ap = (uint2*)smem_raw;                          // 72*72*8 = 41472 B
    __half2* Cp = (__half2*)(smem_raw + TDIM * TDIM * 8);    // 72*72*4 = 20736 B

    const int tx0 = blockIdx.x * TILE;
    const int ty0 = blockIdx.y * TILE;
    const int b   = blockIdx.z;
    const int tid = threadIdx.x;

    const float* img  = fake_S  + (size_t)b * 3 * HW;
    const float* bm   = blurmap + (size_t)b * 2 * HW;
    float*       fb   = out_fb  + (size_t)b * 3 * HW;
    float*       offp = out_off + (size_t)b * 30 * HW;

    // ---- Halo fill: 4 entries/group, float4 loads, named scalars only ----
    // Entry j of a group stores pixels (gx0+j, gx0+j+1); the group needs the
    // 5 pixels gx0..gx0+4 per channel: one aligned float4 + one scalar.
    const int GROUPS = TDIM * (TDIM / 4);   // 72 * 18 = 1296
    #pragma unroll 2
    for (int g = tid; g < GROUPS; g += NTHREADS) {
        int r   = g / (TDIM / 4);
        int q   = g - r * (TDIM / 4);
        int cc0 = q * 4;
        int gy  = ty0 - HALO + r;
        int gx0 = tx0 - HALO + cc0;        // always == 0 mod 4

        float4 v0 = make_float4(0.f, 0.f, 0.f, 0.f);
        float4 v1 = v0, v2 = v0;
        float e0 = 0.f, e1 = 0.f, e2 = 0.f;

        if ((unsigned)gy < (unsigned)H) {
            if ((unsigned)gx0 < (unsigned)W) {   // aligned: fully in or out
                int gi = gy * W + gx0;
                v0 = *(const float4*)(img + gi);
                v1 = *(const float4*)(img + gi + HW);
                v2 = *(const float4*)(img + gi + 2 * HW);
            }
            if ((unsigned)(gx0 + 4) < (unsigned)W) {
                int gi = gy * W + gx0 + 4;
                e0 = __ldg(img + gi);
                e1 = __ldg(img + gi + HW);
                e2 = __ldg(img + gi + 2 * HW);
            }
        }

        // Pack: Ap entry j = (c0,c1)@px j, (c0,c1)@px j+1 ; Cp entry j = (c2)@j,j+1
        __half2 a0 = __floats2half2_rn(v0.x, v1.x);
        __half2 a1 = __floats2half2_rn(v0.y, v1.y);
        __half2 a2 = __floats2half2_rn(v0.z, v1.z);
        __half2 a3 = __floats2half2_rn(v0.w, v1.w);
        __half2 a4 = __floats2half2_rn(e0,   e1);

        uint4 wA0, wA1;
        wA0.x = *(unsigned int*)&a0;  wA0.y = *(unsigned int*)&a1;   // entry 0
        wA0.z = *(unsigned int*)&a1;  wA0.w = *(unsigned int*)&a2;   // entry 1
        wA1.x = *(unsigned int*)&a2;  wA1.y = *(unsigned int*)&a3;   // entry 2
        wA1.z = *(unsigned int*)&a3;  wA1.w = *(unsigned int*)&a4;   // entry 3

        __half2 c01 = __floats2half2_rn(v2.x, v2.y);
        __half2 c12 = __floats2half2_rn(v2.y, v2.z);
        __half2 c23 = __floats2half2_rn(v2.z, v2.w);
        __half2 c34 = __floats2half2_rn(v2.w, e2);
        uint4 wC;
        wC.x = *(unsigned int*)&c01;
        wC.y = *(unsigned int*)&c12;
        wC.z = *(unsigned int*)&c23;
        wC.w = *(unsigned int*)&c34;

        int base = r * TDIM + cc0;
        *(uint4*)(Ap + base)     = wA0;   // STS.128
        *(uint4*)(Ap + base + 2) = wA1;   // STS.128
        *(uint4*)(Cp + base)     = wC;    // STS.128
    }
    __syncthreads();

    const float wgt = __ldg(weight) * (1.0f / 15.0f);
    const float bs  = __ldg(bias);

    // ---- Blur loop: R3 verbatim (interleaved offset stores, int addr) ----
    #pragma unroll 1
    for (int i = 0; i < (TILE * TILE) / NTHREADS; i++) {
        int p  = i * NTHREADS + tid;
        int yl = p >> 5;
        int xl = p & 31;
        int gy = ty0 + yl;
        int gx = tx0 + xl;
        int gidx = gy * W + gx;

        float ob0 = 20.0f * __ldg(bm + gidx);        // dy scale (ch0)
        float ob1 = 20.0f * __ldg(bm + gidx + HW);   // dx scale (ch1)

        // k = 7 (t = 0): exact center sample, zero offsets
        int cbase = (yl + HALO) * TDIM + (xl + HALO);
        uint2 cw = Ap[cbase];
        float2 cl = __half22float2(*(__half2*)&cw.x);
        float2 cz = __half22float2(Cp[cbase]);
        float s0 = cl.x, s1 = cl.y, s2 = cz.x;
        offp[14 * HW + gidx] = 0.f;
        offp[15 * HW + gidx] = 0.f;

        #pragma unroll
        for (int k = 0; k < 15; k++) {
            if (k == 7) continue;
            const float t = (float)(7 - k) / 7.0f;   // compile-time constant
            float oy = t * ob0;
            float ox = t * ob1;
            offp[(2 * k) * HW + gidx]     = oy;
            offp[(2 * k + 1) * HW + gidx] = ox;

            float fy  = (float)gy + oy;              // global coords = ref rounding
            float fx  = (float)gx + ox;
            float fy0 = floorf(fy);
            float fx0 = floorf(fx);
            float tyf = fy - fy0;
            float txf = fx - fx0;
            int iy = (int)fy0 - ty0 + HALO;
            int ix = (int)fx0 - tx0 + HALO;
            int base2 = iy * TDIM + ix;

            uint2   w0 = Ap[base2];            // row y0: (c0,c1)@x0,x1
            uint2   w1 = Ap[base2 + TDIM];     // row y1
            __half2 z0 = Cp[base2];            // c2@(x0,x1), row y0
            __half2 z1 = Cp[base2 + TDIM];     // row y1

            float2 p00 = __half22float2(*(__half2*)&w0.x);
            float2 p01 = __half22float2(*(__half2*)&w0.y);
            float2 p10 = __half22float2(*(__half2*)&w1.x);
            float2 p11 = __half22float2(*(__half2*)&w1.y);
            float2 q0  = __half22float2(z0);
            float2 q1  = __half22float2(z1);

            float w11f = tyf * txf;
            float w10f = tyf - w11f;
            float w01f = txf - w11f;
            float w00f = 1.0f - tyf - txf + w11f;

            s0 = fmaf(w00f, p00.x, s0); s0 = fmaf(w01f, p01.x, s0);
            s0 = fmaf(w10f, p10.x, s0); s0 = fmaf(w11f, p11.x, s0);
            s1 = fmaf(w00f, p00.y, s1); s1 = fmaf(w01f, p01.y, s1);
            s1 = fmaf(w10f, p10.y, s1); s1 = fmaf(w11f, p11.y, s1);
            s2 = fmaf(w00f, q0.x, s2);  s2 = fmaf(w01f, q0.y, s2);
            s2 = fmaf(w10f, q1.x, s2);  s2 = fmaf(w11f, q1.y, s2);
        }

        fb[gidx]          = fmaf(wgt, s0, bs);
        fb[gidx + HW]     = fmaf(wgt, s1, bs);
        fb[gidx + 2 * HW] = fmaf(wgt, s2, bs);
    }
}

extern "C" void kernel_launch(void* const* d_in, const int* in_sizes, int n_in,
                              void* d_out, int out_size)
{
    const float* fake_S  = (const float*)d_in[0];
    const float* blurmap = (const float*)d_in[1];
    const float* weight  = (const float*)d_in[2];
    const float* bias    = (const float*)d_in[3];

    float* out_fb  = (float*)d_out;
    float* out_off = (float*)d_out + (size_t)BATCH * 3 * HW;

    const int smem = TDIM * TDIM * 12;   // 62,208 B
    static bool configured = false;
    if (!configured) {
        cudaFuncSetAttribute(blurnet_kernel,
                             cudaFuncAttributeMaxDynamicSharedMemorySize, smem);
        configured = true;
    }

    dim3 grid(W / TILE, H / TILE, BATCH);   // (8, 8, 8)
    blurnet_kernel<<<grid, NTHREADS, smem>>>(fake_S, blurmap, weight, bias,
                                             out_fb, out_off);
}

// round 10
// speedup vs baseline: 1.1998x; 1.1998x over previous
#include <cuda_runtime.h>
#include <cuda_fp16.h>

// BlurNet: fake_B = w * mean_k bilinear(fake_S, pix + t_k*20*blurmap) + bias
//          offsets_flat[b, 2k+c] = t_k * 20 * blurmap[b, c],  t_k = (7-k)/7
// B=8, C=3, H=W=256. Output: fake_B (B*3*H*W) then offsets (B*30*H*W), f32.
//
// R10 = R7 shape (64x32 tile, 512 thr, 2 CTAs/SM: 32 warps/SM, halo LDG -28%,
// grid 256) + R3 blur loop (offset STGs interleaved in the gather loop — every
// phase-separated variant measured +1..2us) + R3 scalar fill (R9's vectorized
// fill regressed). Gather layout: Ap[i]=(c0,c1)@x0,x1 8B LDS.64;
// Cp[i]=(c2)@x0,x1 4B LDS.32.

#define H 256
#define W 256
#define HW (H * W)
#define BATCH 8
#define TX 64
#define TY 32
#define HALO 20
#define TDX (TX + 2 * HALO)      // 104
#define TDY (TY + 2 * HALO)      // 72
#define NTHREADS 512

__global__ __launch_bounds__(NTHREADS, 2)
void blurnet_kernel(const float* __restrict__ fake_S,
                    const float* __restrict__ blurmap,
                    const float* __restrict__ weight,
                    const float* __restrict__ bias,
                    float* __restrict__ out_fb,
                    float* __restrict__ out_off)
{
    extern __shared__ __align__(16) unsigned char smem_raw[];
    uint2*   Ap = (uint2*)smem_raw;                         // 72*104*8 = 59904 B
    __half2* Cp = (__half2*)(smem_raw + TDY * TDX * 8);     // 72*104*4 = 29952 B

    const int tx0 = blockIdx.x * TX;
    const int ty0 = blockIdx.y * TY;
    const int b   = blockIdx.z;
    const int tid = threadIdx.x;

    const float* img  = fake_S  + (size_t)b * 3 * HW;
    const float* bm   = blurmap + (size_t)b * 2 * HW;
    float*       fb   = out_fb  + (size_t)b * 3 * HW;
    float*       offp = out_off + (size_t)b * 30 * HW;

    // ---- Halo fill: R3-proven scalar path ----
    #pragma unroll 3
    for (int p = tid; p < TDY * TDX; p += NTHREADS) {
        int r  = p / TDX;
        int cc = p - r * TDX;
        int gy = ty0 - HALO + r;
        int gx = tx0 - HALO + cc;
        float v0 = 0.f, v1 = 0.f, v2 = 0.f;   // (gy, gx)
        float u0 = 0.f, u1 = 0.f, u2 = 0.f;   // (gy, gx+1)
        bool rowok = (unsigned)gy < (unsigned)H;
        if (rowok && (unsigned)gx < (unsigned)W) {
            int gi = gy * W + gx;
            v0 = __ldg(img + gi);
            v1 = __ldg(img + gi + HW);
            v2 = __ldg(img + gi + 2 * HW);
        }
        if (rowok && (unsigned)(gx + 1) < (unsigned)W) {
            int gi = gy * W + gx + 1;
            u0 = __ldg(img + gi);
            u1 = __ldg(img + gi + HW);
            u2 = __ldg(img + gi + 2 * HW);
        }
        __half2 lo = __floats2half2_rn(v0, v1);
        __half2 hi = __floats2half2_rn(u0, u1);
        uint2 w;
        w.x = *(unsigned int*)&lo;
        w.y = *(unsigned int*)&hi;
        Ap[p] = w;
        Cp[p] = __floats2half2_rn(v2, u2);
    }
    __syncthreads();

    const float wgt = __ldg(weight) * (1.0f / 15.0f);
    const float bs  = __ldg(bias);

    // ---- Blur loop: R3 verbatim (interleaved offset stores, int addr) ----
    #pragma unroll 1
    for (int i = 0; i < (TX * TY) / NTHREADS; i++) {
        int p  = i * NTHREADS + tid;
        int yl = p >> 6;              // 0..31
        int xl = p & 63;              // 0..63
        int gy = ty0 + yl;
        int gx = tx0 + xl;
        int gidx = gy * W + gx;

        float ob0 = 20.0f * __ldg(bm + gidx);        // dy scale (ch0)
        float ob1 = 20.0f * __ldg(bm + gidx + HW);   // dx scale (ch1)

        // k = 7 (t = 0): exact center sample, zero offsets
        int cbase = (yl + HALO) * TDX + (xl + HALO);
        uint2 cw = Ap[cbase];
        float2 cl = __half22float2(*(__half2*)&cw.x);
        float2 cz = __half22float2(Cp[cbase]);
        float s0 = cl.x, s1 = cl.y, s2 = cz.x;
        offp[14 * HW + gidx] = 0.f;
        offp[15 * HW + gidx] = 0.f;

        #pragma unroll
        for (int k = 0; k < 15; k++) {
            if (k == 7) continue;
            const float t = (float)(7 - k) / 7.0f;   // compile-time constant
            float oy = t * ob0;
            float ox = t * ob1;
            offp[(2 * k) * HW + gidx]     = oy;
            offp[(2 * k + 1) * HW + gidx] = ox;

            float fy  = (float)gy + oy;              // global coords = ref rounding
            float fx  = (float)gx + ox;
            float fy0 = floorf(fy);
            float fx0 = floorf(fx);
            float tyf = fy - fy0;
            float txf = fx - fx0;
            int iy = (int)fy0 - ty0 + HALO;
            int ix = (int)fx0 - tx0 + HALO;
            int base2 = iy * TDX + ix;

            uint2   w0 = Ap[base2];           // row y0: (c0,c1)@x0,x1
            uint2   w1 = Ap[base2 + TDX];     // row y1
            __half2 z0 = Cp[base2];           // c2@(x0,x1), row y0
            __half2 z1 = Cp[base2 + TDX];     // row y1

            float2 p00 = __half22float2(*(__half2*)&w0.x);
            float2 p01 = __half22float2(*(__half2*)&w0.y);
            float2 p10 = __half22float2(*(__half2*)&w1.x);
            float2 p11 = __half22float2(*(__half2*)&w1.y);
            float2 q0  = __half22float2(z0);
            float2 q1  = __half22float2(z1);

            float w11f = tyf * txf;
            float w10f = tyf - w11f;
            float w01f = txf - w11f;
            float w00f = 1.0f - tyf - txf + w11f;

            s0 = fmaf(w00f, p00.x, s0); s0 = fmaf(w01f, p01.x, s0);
            s0 = fmaf(w10f, p10.x, s0); s0 = fmaf(w11f, p11.x, s0);
            s1 = fmaf(w00f, p00.y, s1); s1 = fmaf(w01f, p01.y, s1);
            s1 = fmaf(w10f, p10.y, s1); s1 = fmaf(w11f, p11.y, s1);
            s2 = fmaf(w00f, q0.x, s2);  s2 = fmaf(w01f, q0.y, s2);
            s2 = fmaf(w10f, q1.x, s2);  s2 = fmaf(w11f, q1.y, s2);
        }

        fb[gidx]          = fmaf(wgt, s0, bs);
        fb[gidx + HW]     = fmaf(wgt, s1, bs);
        fb[gidx + 2 * HW] = fmaf(wgt, s2, bs);
    }
}

extern "C" void kernel_launch(void* const* d_in, const int* in_sizes, int n_in,
                              void* d_out, int out_size)
{
    const float* fake_S  = (const float*)d_in[0];
    const float* blurmap = (const float*)d_in[1];
    const float* weight  = (const float*)d_in[2];
    const float* bias    = (const float*)d_in[3];

    float* out_fb  = (float*)d_out;
    float* out_off = (float*)d_out + (size_t)BATCH * 3 * HW;

    const int smem = TDY * TDX * 12;   // 89,856 B
    static bool configured = false;
    if (!configured) {
        cudaFuncSetAttribute(blurnet_kernel,
                             cudaFuncAttributeMaxDynamicSharedMemorySize, smem);
        configured = true;
    }

    dim3 grid(W / TX, H / TY, BATCH);   // (4, 8, 8) = 256 CTAs
    blurnet_kernel<<<grid, NTHREADS, smem>>>(fake_S, blurmap, weight, bias,
                                             out_fb, out_off);
}